// round 5
// baseline (speedup 1.0000x reference)
#include <cuda_runtime.h>
#include <cuda_fp16.h>

#define N_ROWS 131072
#define ND 13
#define NS 26
#define NF 39
#define EMB 16
#define DDIM 624   // NF*EMB
#define HID 32
#define VOCAB 100000
#define EPSF 1e-5f

#define TILE 32
#define BLK 256
#define GRID_A 152
#define NTILES (N_ROWS/TILE)
#define DSTRIDE 628             // floats per deep row (pad)
#define WSTRIDE 628             // floats per Wl1T column

// smem float offsets
#define OFF_WL1T   0
#define OFF_DEEP   20096
#define OFF_W1D    40192
#define OFF_B1D    40400
#define OFF_W2D    40608
#define OFF_B2D    40816
#define OFF_XV     41024
#define OFF_XID    42272
#define OFF_XIS    42688
#define SMEM_FLOATS 43520
#define SMEM_BYTES (SMEM_FLOATS*4)

// Scratch device globals (no allocation allowed)
__device__ __half g_x1h[(size_t)N_ROWS*HID];
__device__ float g_S1[HID];
__device__ float g_S2[HID*HID];
__device__ float g_w[HID];
__device__ float g_C;

typedef unsigned long long ull;

__device__ __forceinline__ ull ffma2(ull a, ull b, ull c) {
    ull d;
    asm("fma.rn.f32x2 %0, %1, %2, %3;" : "=l"(d) : "l"(a), "l"(b), "l"(c));
    return d;
}
__device__ __forceinline__ float ull_sum2(ull v) {
    float lo = __uint_as_float((unsigned)(v & 0xffffffffULL));
    float hi = __uint_as_float((unsigned)(v >> 32));
    return lo + hi;
}

__global__ void k_init() {
    int t = threadIdx.x;
    for (int i = t; i < HID*HID; i += blockDim.x) g_S2[i] = 0.f;
    if (t < HID) g_S1[t] = 0.f;
}

__global__ void __launch_bounds__(BLK,1) k_main(
    const float* __restrict__ Xi_d, const int* __restrict__ Xi_s,
    const float* __restrict__ Xv,   const float* __restrict__ bias,
    const float* __restrict__ W1d,  const float* __restrict__ b1d,
    const float* __restrict__ T1,
    const float* __restrict__ W2d,  const float* __restrict__ b2d,
    const float* __restrict__ T2,
    const float* __restrict__ Wl1,  const float* __restrict__ bl1,
    float* __restrict__ out)
{
    extern __shared__ float smem[];
    float* Wl1Ts = smem + OFF_WL1T;
    float* deeps = smem + OFF_DEEP;
    float4* sW1d4 = (float4*)(smem + OFF_W1D);
    float4* sB1d4 = (float4*)(smem + OFF_B1D);
    float4* sW2d4 = (float4*)(smem + OFF_W2D);
    float4* sB2d4 = (float4*)(smem + OFF_B2D);
    float*  sXv   = smem + OFF_XV;
    float*  sXid  = smem + OFF_XID;
    int*    sXis  = (int*)(smem + OFF_XIS);

    int tid = threadIdx.x;
    int lane = tid & 31, wid = tid >> 5;

    // ---- one-time block init: transpose Wl1 into smem, cache dense weights ----
    {
        int col = lane, dr = wid;           // 8 warps cover d in steps of 8
        for (int d = dr; d < DDIM; d += 8)
            Wl1Ts[col*WSTRIDE + d] = Wl1[d*HID + col];
        if (tid < 52) {
            sW1d4[tid] = ((const float4*)W1d)[tid];
            sB1d4[tid] = ((const float4*)b1d)[tid];
            sW2d4[tid] = ((const float4*)W2d)[tid];
            sB2d4[tid] = ((const float4*)b2d)[tid];
        }
    }

    float bl1v = bl1[lane];
    float s1p = 0.f;
    float s2p[HID];
    #pragma unroll
    for (int i = 0; i < HID; i++) s2p[i] = 0.f;

    int rr = lane >> 3;          // row within warp's 4
    int e  = (lane >> 2) & 1;    // field-pair selector
    int p  = lane & 3;           // 16B piece within 64B entry
    int rl = wid*4 + rr;         // row within tile (0..31)

    for (int tile = blockIdx.x; tile < NTILES; tile += gridDim.x) {
        int row0 = tile * TILE;

        // ---------------- stage tile inputs (coalesced) ----------------
        {
            const float4* gXv = (const float4*)(Xv   + row0*NF);
            const float4* gXd = (const float4*)(Xi_d + row0*ND);
            const int4*   gXs = (const int4*)  (Xi_s + row0*NS);
            float4* dXv = (float4*)sXv;
            float4* dXd = (float4*)sXid;
            int4*   dXs = (int4*)sXis;
            for (int i = tid; i < 312; i += BLK) dXv[i] = gXv[i];   // 32*39/4
            if (tid < 104) dXd[tid] = gXd[tid];                     // 32*13/4
            if (tid < 208) dXs[tid] = gXs[tid];                     // 32*26/4
        }
        __syncthreads();   // stage visible; also: all warps done with prev GEMM reads of deeps

        // ---------------- gather / embed phase ----------------
        {
            int row = row0 + rl;
            float4 s4 = {0,0,0,0};
            float sq = 0.f, fst = 0.f;
            const int*   xisrow = sXis + rl*NS;
            const float* xvsp   = sXv  + rl*NF + ND;
            float* drow = deeps + rl*DSTRIDE;

            // sparse: both tables, 2 fields per warp-pass, 4 lanes per entry
            #pragma unroll
            for (int it = 0; it < 13; it++) {
                int sf = it*2 + e;
                int idx = xisrow[sf];
                float xv = xvsp[sf];
                size_t base = ((size_t)sf*VOCAB + idx) * EMB;
                float4 a = ((const float4*)(T2 + base))[p];
                float4 b = ((const float4*)(T1 + base))[p];
                float4 v = make_float4(a.x*xv, a.y*xv, a.z*xv, a.w*xv);
                ((float4*)(drow + (ND+sf)*EMB))[p] = v;
                s4.x += v.x; s4.y += v.y; s4.z += v.z; s4.w += v.w;
                sq = fmaf(v.x,v.x,sq); sq = fmaf(v.y,v.y,sq);
                sq = fmaf(v.z,v.z,sq); sq = fmaf(v.w,v.w,sq);
                fst = fmaf(xv, b.x+b.y+b.z+b.w, fst);
            }
            // dense fields, same decomposition (f = it*2+e, guard f<13)
            #pragma unroll
            for (int it = 0; it < 7; it++) {
                int f = it*2 + e;
                if (f < ND) {
                    float xd = sXid[rl*ND + f];
                    float xv = sXv[rl*NF + f];
                    float4 w2 = sW2d4[f*4+p], c2 = sB2d4[f*4+p];
                    float4 v;
                    v.x = fmaf(xd,w2.x,c2.x)*xv; v.y = fmaf(xd,w2.y,c2.y)*xv;
                    v.z = fmaf(xd,w2.z,c2.z)*xv; v.w = fmaf(xd,w2.w,c2.w)*xv;
                    ((float4*)(drow + f*EMB))[p] = v;
                    s4.x += v.x; s4.y += v.y; s4.z += v.z; s4.w += v.w;
                    sq = fmaf(v.x,v.x,sq); sq = fmaf(v.y,v.y,sq);
                    sq = fmaf(v.z,v.z,sq); sq = fmaf(v.w,v.w,sq);
                    float4 w1 = sW1d4[f*4+p], c1 = sB1d4[f*4+p];
                    float t = fmaf(xd,w1.x,c1.x) + fmaf(xd,w1.y,c1.y)
                            + fmaf(xd,w1.z,c1.z) + fmaf(xd,w1.w,c1.w);
                    fst = fmaf(xv, t, fst);
                }
            }
            // reduce e (offset 4, width 8): s4, sq, fst
            s4.x += __shfl_down_sync(0xffffffffu, s4.x, 4, 8);
            s4.y += __shfl_down_sync(0xffffffffu, s4.y, 4, 8);
            s4.z += __shfl_down_sync(0xffffffffu, s4.z, 4, 8);
            s4.w += __shfl_down_sync(0xffffffffu, s4.w, 4, 8);
            sq  += __shfl_down_sync(0xffffffffu, sq,  4, 8);
            fst += __shfl_down_sync(0xffffffffu, fst, 4, 8);
            // per-piece |s|^2, then reduce pieces + remaining sq/fst
            float dotp = s4.x*s4.x + s4.y*s4.y + s4.z*s4.z + s4.w*s4.w;
            dotp += __shfl_down_sync(0xffffffffu, dotp, 2, 8);
            sq   += __shfl_down_sync(0xffffffffu, sq,   2, 8);
            fst  += __shfl_down_sync(0xffffffffu, fst,  2, 8);
            dotp += __shfl_down_sync(0xffffffffu, dotp, 1, 8);
            sq   += __shfl_down_sync(0xffffffffu, sq,   1, 8);
            fst  += __shfl_down_sync(0xffffffffu, fst,  1, 8);
            if ((lane & 7) == 0)
                out[row] = fst + 0.5f*(dotp - sq) + bias[row];
        }
        __syncthreads();

        // ---------------- GEMM: x1 = deep @ Wl1 + bl1 (f32x2 packed) ----------------
        {
            const ulonglong2* wp  = (const ulonglong2*)(Wl1Ts + lane*WSTRIDE);
            const ulonglong2* dp0 = (const ulonglong2*)(deeps + (wid*4+0)*DSTRIDE);
            const ulonglong2* dp1 = (const ulonglong2*)(deeps + (wid*4+1)*DSTRIDE);
            const ulonglong2* dp2 = (const ulonglong2*)(deeps + (wid*4+2)*DSTRIDE);
            const ulonglong2* dp3 = (const ulonglong2*)(deeps + (wid*4+3)*DSTRIDE);
            ull pa0=0ULL,pb0=0ULL,pa1=0ULL,pb1=0ULL;
            ull pa2=0ULL,pb2=0ULL,pa3=0ULL,pb3=0ULL;
            #pragma unroll 4
            for (int d4 = 0; d4 < DDIM/4; d4++) {
                ulonglong2 w  = wp[d4];
                ulonglong2 x0 = dp0[d4], x1 = dp1[d4], x2 = dp2[d4], x3 = dp3[d4];
                pa0 = ffma2(x0.x, w.x, pa0); pb0 = ffma2(x0.y, w.y, pb0);
                pa1 = ffma2(x1.x, w.x, pa1); pb1 = ffma2(x1.y, w.y, pb1);
                pa2 = ffma2(x2.x, w.x, pa2); pb2 = ffma2(x2.y, w.y, pb2);
                pa3 = ffma2(x3.x, w.x, pa3); pb3 = ffma2(x3.y, w.y, pb3);
            }
            float xr0 = ull_sum2(pa0) + ull_sum2(pb0) + bl1v;
            float xr1 = ull_sum2(pa1) + ull_sum2(pb1) + bl1v;
            float xr2 = ull_sum2(pa2) + ull_sum2(pb2) + bl1v;
            float xr3 = ull_sum2(pa3) + ull_sum2(pb3) + bl1v;
            int rb = row0 + wid*4;
            g_x1h[(size_t)(rb+0)*HID + lane] = __float2half(xr0);
            g_x1h[(size_t)(rb+1)*HID + lane] = __float2half(xr1);
            g_x1h[(size_t)(rb+2)*HID + lane] = __float2half(xr2);
            g_x1h[(size_t)(rb+3)*HID + lane] = __float2half(xr3);
            s1p += xr0 + xr1 + xr2 + xr3;
            #pragma unroll
            for (int i = 0; i < HID; i++) {
                s2p[i] = fmaf(__shfl_sync(0xffffffffu, xr0, i), xr0, s2p[i]);
                s2p[i] = fmaf(__shfl_sync(0xffffffffu, xr1, i), xr1, s2p[i]);
                s2p[i] = fmaf(__shfl_sync(0xffffffffu, xr2, i), xr2, s2p[i]);
                s2p[i] = fmaf(__shfl_sync(0xffffffffu, xr3, i), xr3, s2p[i]);
            }
        }
    }

    // ---------------- block-reduce stats, one atomic per entry ----------------
    __syncthreads();
    float* red = deeps;  // reuse: 8*1024 + 8*32 floats < 20096
    #pragma unroll
    for (int i = 0; i < HID; i++) red[wid*HID*HID + i*HID + lane] = s2p[i];
    red[8*HID*HID + wid*HID + lane] = s1p;
    __syncthreads();
    for (int k = tid; k < HID*HID; k += BLK) {
        float s = 0.f;
        #pragma unroll
        for (int w = 0; w < 8; w++) s += red[w*HID*HID + k];
        atomicAdd(&g_S2[k], s);
    }
    if (tid < HID) {
        float s = 0.f;
        #pragma unroll
        for (int w = 0; w < 8; w++) s += red[8*HID*HID + w*HID + tid];
        atomicAdd(&g_S1[tid], s);
    }
}

// Collapse BN->Linear->BN->rowsum into w (32) and scalar C, in fp64.
__global__ void k_stats(const float* __restrict__ Wl2, const float* __restrict__ bl2,
                        const float* __restrict__ g1,  const float* __restrict__ be1,
                        const float* __restrict__ g2,  const float* __restrict__ be2)
{
    __shared__ double m1s[HID], als[HID], bes[HID], ts[HID];
    __shared__ double Cov[HID][HID];
    int i = threadIdx.x;  // 32 threads
    const double invN = 1.0 / (double)N_ROWS;

    double m1 = (double)g_S1[i] * invN;
    m1s[i] = m1;
    __syncwarp();
    for (int k = 0; k < HID; k++)
        Cov[i][k] = (double)g_S2[i*HID + k] * invN - m1 * m1s[k];
    double v1 = Cov[i][i];
    double al = (double)g1[i] / sqrt(v1 + (double)EPSF);
    double be = (double)be1[i] - al * m1;
    als[i] = al; bes[i] = be;
    __syncwarp();

    int j = i;
    double m2o = 0.0;
    for (int k = 0; k < HID; k++) {
        double wkj = (double)Wl2[k*HID + j];
        m2o += als[k] * wkj * m1s[k];
    }
    double v2 = 0.0;
    for (int a = 0; a < HID; a++) {
        double Ma = als[a] * (double)Wl2[a*HID + j];
        double acc = 0.0;
        for (int b = 0; b < HID; b++)
            acc += Cov[a][b] * (als[b] * (double)Wl2[b*HID + j]);
        v2 += Ma * acc;
    }
    double tj = (double)g2[j] / sqrt(v2 + (double)EPSF);
    ts[j] = tj;
    __syncwarp();

    // per-row constant contribution: the additive (cj) part of x2 cancels with
    // its own mean inside BN, leaving C_j = -t_j * m2o_j + be2_j.
    double Cj = -tj * m2o + (double)be2[j];

    double wsum = 0.0;
    for (int j2 = 0; j2 < HID; j2++) wsum += (double)Wl2[i*HID + j2] * ts[j2];
    g_w[i] = (float)(als[i] * wsum);

    double c = Cj;
    #pragma unroll
    for (int off = 16; off; off >>= 1) c += __shfl_down_sync(0xffffffffu, c, off);
    if (i == 0) g_C = (float)c;
}

__global__ void k_final(float* __restrict__ out) {
    __shared__ float ws[HID];
    __shared__ float Cs;
    if (threadIdx.x < HID) ws[threadIdx.x] = g_w[threadIdx.x];
    if (threadIdx.x == 0)  Cs = g_C;
    __syncthreads();
    int row = blockIdx.x * blockDim.x + threadIdx.x;
    const uint4* xq = (const uint4*)(g_x1h + (size_t)row * HID);  // 4 x 16B = 32 halfs
    float acc = Cs;
    #pragma unroll
    for (int q = 0; q < 4; q++) {
        uint4 u = xq[q];
        unsigned uu[4] = {u.x, u.y, u.z, u.w};
        #pragma unroll
        for (int h = 0; h < 4; h++) {
            __half2 hv = *(__half2*)&uu[h];
            float2 f = __half22float2(hv);
            acc = fmaf(f.x, ws[q*8 + h*2 + 0], acc);
            acc = fmaf(f.y, ws[q*8 + h*2 + 1], acc);
        }
    }
    out[row] += acc;
}

extern "C" void kernel_launch(void* const* d_in, const int* in_sizes, int n_in,
                              void* d_out, int out_size)
{
    const float* Xi_d = (const float*)d_in[0];
    const int*   Xi_s = (const int*)  d_in[1];
    const float* Xv   = (const float*)d_in[2];
    const float* bias = (const float*)d_in[3];
    const float* W1d  = (const float*)d_in[4];
    const float* b1d  = (const float*)d_in[5];
    const float* T1   = (const float*)d_in[6];
    const float* W2d  = (const float*)d_in[7];
    const float* b2d  = (const float*)d_in[8];
    const float* T2   = (const float*)d_in[9];
    const float* Wl1  = (const float*)d_in[10];
    const float* bl1  = (const float*)d_in[11];
    const float* g1   = (const float*)d_in[12];
    const float* be1  = (const float*)d_in[13];
    const float* Wl2  = (const float*)d_in[14];
    const float* bl2  = (const float*)d_in[15];
    const float* g2   = (const float*)d_in[16];
    const float* be2  = (const float*)d_in[17];
    float* out = (float*)d_out;

    cudaFuncSetAttribute(k_main, cudaFuncAttributeMaxDynamicSharedMemorySize, SMEM_BYTES);

    k_init<<<1, 256>>>();
    k_main<<<GRID_A, BLK, SMEM_BYTES>>>(Xi_d, Xi_s, Xv, bias,
                                        W1d, b1d, T1, W2d, b2d, T2,
                                        Wl1, bl1, out);
    k_stats<<<1, 32>>>(Wl2, bl2, g1, be1, g2, be2);
    k_final<<<N_ROWS/256, 256>>>(out);
}

// round 7
// speedup vs baseline: 1.4032x; 1.4032x over previous
#include <cuda_runtime.h>
#include <cuda_fp16.h>

#define N_ROWS 131072
#define ND 13
#define NS 26
#define NF 39
#define EMB 16
#define DDIM 624
#define HID 32
#define VOCAB 100000
#define EPSF 1e-5f

#define TILE 32
#define BLK 256
#define GRID_A 148
#define NTILES (N_ROWS/TILE)
#define DSTRIDE 628          // fp32 floats per deep row
#define WH_STRIDE 636        // halfs per weight column (pad: conflict-free LDS.64)

// smem float offsets
#define OFF_W1H   0                       // 32*636 halfs = 10176 floats
#define OFF_DB0   10176                   // 32*628 = 20096 floats
#define OFF_DB1   30272                   // 20096 floats
#define OFF_W1D   50368                   // 208
#define OFF_B1D   50576
#define OFF_W2D   50784
#define OFF_B2D   50992
#define SMEM_FLOATS 51200
#define SMEM_BYTES (SMEM_FLOATS*4)        // 204800 B

__device__ float g_x1[(size_t)N_ROWS*HID];
__device__ float g_S1[HID];
__device__ float g_S2[HID*HID];
__device__ float g_w[HID];
__device__ float g_C;

typedef unsigned long long ull;

__device__ __forceinline__ ull ffma2(ull a, ull b, ull c) {
    ull d;
    asm("fma.rn.f32x2 %0, %1, %2, %3;" : "=l"(d) : "l"(a), "l"(b), "l"(c));
    return d;
}
__device__ __forceinline__ float ull_sum2(ull v) {
    float lo = __uint_as_float((unsigned)(v & 0xffffffffULL));
    float hi = __uint_as_float((unsigned)(v >> 32));
    return lo + hi;
}
__device__ __forceinline__ ull packf2(float lo, float hi) {
    ull r;
    asm("mov.b64 %0, {%1, %2};" : "=l"(r) : "f"(lo), "f"(hi));
    return r;
}

__global__ void k_init() {
    int t = threadIdx.x;
    for (int i = t; i < HID*HID; i += blockDim.x) g_S2[i] = 0.f;
    if (t < HID) g_S1[t] = 0.f;
}

__global__ void __launch_bounds__(BLK,1) k_main(
    const float* __restrict__ Xi_d, const int* __restrict__ Xi_s,
    const float* __restrict__ Xv,   const float* __restrict__ bias,
    const float* __restrict__ W1d,  const float* __restrict__ b1d,
    const float* __restrict__ T1,
    const float* __restrict__ W2d,  const float* __restrict__ b2d,
    const float* __restrict__ T2,
    const float* __restrict__ Wl1,  const float* __restrict__ bl1,
    float* __restrict__ out)
{
    extern __shared__ float smem[];
    __half* Wl1h  = (__half*)(smem + OFF_W1H);
    float4* sW1d4 = (float4*)(smem + OFF_W1D);
    float4* sB1d4 = (float4*)(smem + OFF_B1D);
    float4* sW2d4 = (float4*)(smem + OFF_W2D);
    float4* sB2d4 = (float4*)(smem + OFF_B2D);

    int tid = threadIdx.x;
    int lane = tid & 31, wid = tid >> 5;
    int bid = blockIdx.x;

    // ---- one-time: Wl1 -> fp16 transposed [col][d]; dense weights -> smem ----
    for (int d = wid; d < DDIM; d += 8)
        Wl1h[lane*WH_STRIDE + d] = __float2half(Wl1[d*HID + lane]);
    if (tid < 52) {
        sW1d4[tid] = ((const float4*)W1d)[tid];
        sB1d4[tid] = ((const float4*)b1d)[tid];
        sW2d4[tid] = ((const float4*)W2d)[tid];
        sB2d4[tid] = ((const float4*)b2d)[tid];
    }

    float bl1v = bl1[lane];
    float s1p = 0.f;
    float s2p[HID];
    #pragma unroll
    for (int i = 0; i < HID; i++) s2p[i] = 0.f;

    // producer mapping (warps 0-3): 128 threads = 32 rows x 4 pieces
    int p_row = tid >> 2;       // 0..31 (valid for tid<128)
    int p     = tid & 3;        // 16B piece of 64B entry
    // consumer mapping (warps 4-7): warp handles 8 rows, lane = output column
    int c_wid = wid - 4;

    int ntb = (NTILES - bid + GRID_A - 1) / GRID_A;   // tiles for this block

    for (int i = 0; i <= ntb; i++) {
        __syncthreads();
        if (wid < 4) {
            // ======== PRODUCER: gather tile i into buf(i&1) ========
            if (i < ntb) {
                int t = bid + i*GRID_A;
                int row = t*TILE + p_row;
                float* drow = smem + ((i & 1) ? OFF_DB1 : OFF_DB0) + p_row*DSTRIDE;
                const int*   xis = Xi_s + row*NS;
                const float* xvp = Xv   + row*NF;

                float4 s4 = {0.f,0.f,0.f,0.f};
                float sq = 0.f, fst = 0.f;

                // sparse fields: T2 (deep/FM) + T1 (first-order), 4 lanes per entry
                #pragma unroll
                for (int sf = 0; sf < NS; sf++) {
                    int idx  = __ldg(xis + sf);
                    float xv = __ldg(xvp + ND + sf);
                    size_t base = ((size_t)sf*VOCAB + idx) * EMB;
                    float4 a = ((const float4*)(T2 + base))[p];
                    float4 b = ((const float4*)(T1 + base))[p];
                    float4 v = make_float4(a.x*xv, a.y*xv, a.z*xv, a.w*xv);
                    ((float4*)(drow + (ND+sf)*EMB))[p] = v;
                    s4.x += v.x; s4.y += v.y; s4.z += v.z; s4.w += v.w;
                    sq = fmaf(v.x,v.x,sq); sq = fmaf(v.y,v.y,sq);
                    sq = fmaf(v.z,v.z,sq); sq = fmaf(v.w,v.w,sq);
                    fst = fmaf(xv, b.x+b.y+b.z+b.w, fst);
                }
                // dense fields
                #pragma unroll
                for (int f = 0; f < ND; f++) {
                    float xd = __ldg(Xi_d + row*ND + f);
                    float xv = __ldg(xvp + f);
                    float4 w2 = sW2d4[f*4+p], c2 = sB2d4[f*4+p];
                    float4 v;
                    v.x = fmaf(xd,w2.x,c2.x)*xv; v.y = fmaf(xd,w2.y,c2.y)*xv;
                    v.z = fmaf(xd,w2.z,c2.z)*xv; v.w = fmaf(xd,w2.w,c2.w)*xv;
                    ((float4*)(drow + f*EMB))[p] = v;
                    s4.x += v.x; s4.y += v.y; s4.z += v.z; s4.w += v.w;
                    sq = fmaf(v.x,v.x,sq); sq = fmaf(v.y,v.y,sq);
                    sq = fmaf(v.z,v.z,sq); sq = fmaf(v.w,v.w,sq);
                    float4 w1 = sW1d4[f*4+p], c1 = sB1d4[f*4+p];
                    float tt = fmaf(xd,w1.x,c1.x) + fmaf(xd,w1.y,c1.y)
                             + fmaf(xd,w1.z,c1.z) + fmaf(xd,w1.w,c1.w);
                    fst = fmaf(xv, tt, fst);
                }
                // reduce over 4 piece-lanes
                float dotp = s4.x*s4.x + s4.y*s4.y + s4.z*s4.z + s4.w*s4.w;
                dotp += __shfl_down_sync(0xffffffffu, dotp, 2, 4);
                sq   += __shfl_down_sync(0xffffffffu, sq,   2, 4);
                fst  += __shfl_down_sync(0xffffffffu, fst,  2, 4);
                dotp += __shfl_down_sync(0xffffffffu, dotp, 1, 4);
                sq   += __shfl_down_sync(0xffffffffu, sq,   1, 4);
                fst  += __shfl_down_sync(0xffffffffu, fst,  1, 4);
                if (p == 0)
                    out[row] = fst + 0.5f*(dotp - sq) + __ldg(bias + row);
            }
        } else {
            // ======== CONSUMER: GEMM tile i-1 from buf((i-1)&1) ========
            if (i >= 1) {
                int t = bid + (i-1)*GRID_A;
                const float* dbase = smem + (((i-1) & 1) ? OFF_DB1 : OFF_DB0);
                const ulonglong2* dp[8];
                #pragma unroll
                for (int r = 0; r < 8; r++)
                    dp[r] = (const ulonglong2*)(dbase + (c_wid*8 + r)*DSTRIDE);
                const uint2* wp = (const uint2*)(Wl1h + lane*WH_STRIDE);

                ull acc[8];
                #pragma unroll
                for (int r = 0; r < 8; r++) acc[r] = 0ULL;

                #pragma unroll 4
                for (int d4 = 0; d4 < DDIM/4; d4++) {
                    uint2 wh = wp[d4];
                    float2 w01 = __half22float2(*(__half2*)&wh.x);
                    float2 w23 = __half22float2(*(__half2*)&wh.y);
                    ull W01 = packf2(w01.x, w01.y);
                    ull W23 = packf2(w23.x, w23.y);
                    #pragma unroll
                    for (int r = 0; r < 8; r++) {
                        ulonglong2 x = dp[r][d4];
                        acc[r] = ffma2(x.x, W01, acc[r]);
                        acc[r] = ffma2(x.y, W23, acc[r]);
                    }
                }
                int rowg = t*TILE + c_wid*8;
                #pragma unroll
                for (int r = 0; r < 8; r++) {
                    float xr = ull_sum2(acc[r]) + bl1v;
                    g_x1[(size_t)(rowg + r)*HID + lane] = xr;
                    s1p += xr;
                    #pragma unroll
                    for (int j = 0; j < HID; j++)
                        s2p[j] = fmaf(__shfl_sync(0xffffffffu, xr, j), xr, s2p[j]);
                }
            }
        }
    }

    // ---------------- block-reduce stats, one atomic per entry ----------------
    __syncthreads();
    float* red = smem + OFF_DB0;   // scratch: 8*1024 + 8*32 floats fits
    #pragma unroll
    for (int i = 0; i < HID; i++) red[wid*HID*HID + i*HID + lane] = s2p[i];
    red[8*HID*HID + wid*HID + lane] = s1p;
    __syncthreads();
    for (int k = tid; k < HID*HID; k += BLK) {
        float s = 0.f;
        #pragma unroll
        for (int w = 0; w < 8; w++) s += red[w*HID*HID + k];
        atomicAdd(&g_S2[k], s);
    }
    if (tid < HID) {
        float s = 0.f;
        #pragma unroll
        for (int w = 0; w < 8; w++) s += red[8*HID*HID + w*HID + tid];
        atomicAdd(&g_S1[tid], s);
    }
}

// Collapse BN->Linear->BN->rowsum into w (32) and scalar C, in fp64.
__global__ void k_stats(const float* __restrict__ Wl2, const float* __restrict__ bl2,
                        const float* __restrict__ g1,  const float* __restrict__ be1,
                        const float* __restrict__ g2,  const float* __restrict__ be2)
{
    __shared__ double m1s[HID], als[HID], ts[HID];
    __shared__ double Cov[HID][HID];
    int i = threadIdx.x;  // 32 threads
    const double invN = 1.0 / (double)N_ROWS;

    double m1 = (double)g_S1[i] * invN;
    m1s[i] = m1;
    __syncwarp();
    for (int k = 0; k < HID; k++)
        Cov[i][k] = (double)g_S2[i*HID + k] * invN - m1 * m1s[k];
    double v1 = Cov[i][i];
    double al = (double)g1[i] / sqrt(v1 + (double)EPSF);
    als[i] = al;
    __syncwarp();

    int j = i;
    double m2o = 0.0;
    for (int k = 0; k < HID; k++)
        m2o += als[k] * (double)Wl2[k*HID + j] * m1s[k];
    double v2 = 0.0;
    for (int a = 0; a < HID; a++) {
        double Ma = als[a] * (double)Wl2[a*HID + j];
        double accd = 0.0;
        for (int b = 0; b < HID; b++)
            accd += Cov[a][b] * (als[b] * (double)Wl2[b*HID + j]);
        v2 += Ma * accd;
    }
    double tj = (double)g2[j] / sqrt(v2 + (double)EPSF);
    ts[j] = tj;
    __syncwarp();

    // additive part of x2 cancels against its own batch mean inside BN:
    // C_j = -t_j * m2o_j + be2_j
    double Cj = -tj * m2o + (double)be2[j];

    double wsum = 0.0;
    for (int j2 = 0; j2 < HID; j2++) wsum += (double)Wl2[i*HID + j2] * ts[j2];
    g_w[i] = (float)(als[i] * wsum);

    double c = Cj;
    #pragma unroll
    for (int off = 16; off; off >>= 1) c += __shfl_down_sync(0xffffffffu, c, off);
    if (i == 0) g_C = (float)c;
}

__global__ void k_final(float* __restrict__ out) {
    __shared__ float ws[HID];
    __shared__ float Cs;
    if (threadIdx.x < HID) ws[threadIdx.x] = g_w[threadIdx.x];
    if (threadIdx.x == 0)  Cs = g_C;
    __syncthreads();
    int row = blockIdx.x * blockDim.x + threadIdx.x;
    const float4* xp  = (const float4*)(g_x1 + (size_t)row * HID);
    const float4* wp4 = (const float4*)ws;
    float acc = Cs;
    #pragma unroll
    for (int q = 0; q < 8; q++) {
        float4 x = xp[q], w = wp4[q];
        acc += x.x*w.x + x.y*w.y + x.z*w.z + x.w*w.w;
    }
    out[row] += acc;
}

extern "C" void kernel_launch(void* const* d_in, const int* in_sizes, int n_in,
                              void* d_out, int out_size)
{
    const float* Xi_d = (const float*)d_in[0];
    const int*   Xi_s = (const int*)  d_in[1];
    const float* Xv   = (const float*)d_in[2];
    const float* bias = (const float*)d_in[3];
    const float* W1d  = (const float*)d_in[4];
    const float* b1d  = (const float*)d_in[5];
    const float* T1   = (const float*)d_in[6];
    const float* W2d  = (const float*)d_in[7];
    const float* b2d  = (const float*)d_in[8];
    const float* T2   = (const float*)d_in[9];
    const float* Wl1  = (const float*)d_in[10];
    const float* bl1  = (const float*)d_in[11];
    const float* g1   = (const float*)d_in[12];
    const float* be1  = (const float*)d_in[13];
    const float* Wl2  = (const float*)d_in[14];
    const float* bl2  = (const float*)d_in[15];
    const float* g2   = (const float*)d_in[16];
    const float* be2  = (const float*)d_in[17];
    float* out = (float*)d_out;

    cudaFuncSetAttribute(k_main, cudaFuncAttributeMaxDynamicSharedMemorySize, SMEM_BYTES);

    k_init<<<1, 256>>>();
    k_main<<<GRID_A, BLK, SMEM_BYTES>>>(Xi_d, Xi_s, Xv, bias,
                                        W1d, b1d, T1, W2d, b2d, T2,
                                        Wl1, bl1, out);
    k_stats<<<1, 32>>>(Wl2, bl2, g1, be1, g2, be2);
    k_final<<<N_ROWS/256, 256>>>(out);
}